// round 15
// baseline (speedup 1.0000x reference)
#include <cuda_runtime.h>
#include <cuda_fp16.h>
#include <cstdint>

#define NB   2
#define CIN  128
#define CH   64
#define NPOS 4096
#define JB   32           // 128-wide stat blocks
#define ASPLIT 8

typedef uint32_t u32;

// ================= helpers =================
__device__ __forceinline__ void mma_f16(float c[4], u32 a0, u32 a1, u32 a2, u32 a3,
                                        u32 b0, u32 b1) {
    asm volatile("mma.sync.aligned.m16n8k16.row.col.f32.f16.f16.f32 "
                 "{%0,%1,%2,%3}, {%4,%5,%6,%7}, {%8,%9}, {%0,%1,%2,%3};"
                 : "+f"(c[0]), "+f"(c[1]), "+f"(c[2]), "+f"(c[3])
                 : "r"(a0), "r"(a1), "r"(a2), "r"(a3), "r"(b0), "r"(b1));
}
__device__ __forceinline__ u32 smaddr(const void* p) {
    return (u32)__cvta_generic_to_shared(p);
}
#define LDSM_X4(r0, r1, r2, r3, a) \
    asm volatile("ldmatrix.sync.aligned.m8n8.x4.shared.b16 {%0,%1,%2,%3}, [%4];" \
        : "=r"(r0), "=r"(r1), "=r"(r2), "=r"(r3) : "r"(a))
#define LDSM_X2(r0, r1, a) \
    asm volatile("ldmatrix.sync.aligned.m8n8.x2.shared.b16 {%0,%1}, [%2];" \
        : "=r"(r0), "=r"(r1) : "r"(a))
#define LDSM_X2T(r0, r1, a) \
    asm volatile("ldmatrix.sync.aligned.m8n8.x2.trans.shared.b16 {%0,%1}, [%2];" \
        : "=r"(r0), "=r"(r1) : "r"(a))
__device__ __forceinline__ void cp_async16(u32 dst, const void* src) {
    asm volatile("cp.async.cg.shared.global [%0], [%1], 16;" :: "r"(dst), "l"(src));
}
#define CP_COMMIT() asm volatile("cp.async.commit_group;" ::: "memory")
#define CP_WAIT(n)  asm volatile("cp.async.wait_group %0;" :: "n"(n) : "memory")

// ================= scratch =================
__device__ __half g_kh[NB * NPOS * CH];     // [b][i][c]
__device__ __half g_kl[NB * NPOS * CH];
__device__ __half g_qh[NB * NPOS * CH];     // [b][j][c]
__device__ __half g_ql[NB * NPOS * CH];
__device__ __half g_v [NB * CH * NPOS];     // [b][c][i] single fp16
__device__ __half g_P [(size_t)NB * NPOS * NPOS];   // P_loc = exp(S - m_block128)
__device__ float g_mpart[NB * JB * NPOS];
__device__ float g_spart[NB * JB * NPOS];
__device__ float g_m[NB * NPOS];
__device__ float g_w[NB * NPOS];
__device__ float g_aggp[ASPLIT][NB * CH * NPOS];

// ================= K1: qkv, x read once per block, W in smem =================
// grid (NB, 32, 3), block 128. Each thread: 1 pos, all 64 out-channels.
#define QK_WS 68
__global__ void __launch_bounds__(128) qkv_kernel(
    const float* __restrict__ x,
    const float* __restrict__ Wq,
    const float* __restrict__ Wk,
    const float* __restrict__ Wv)
{
    __shared__ float sW[CIN * QK_WS];      // [c][o] transposed, padded

    int b   = blockIdx.x;
    int pos = blockIdx.y * 128 + threadIdx.x;
    int mat = blockIdx.z;
    const float* W = (mat == 0) ? Wq : (mat == 1) ? Wk : Wv;
    int tid = threadIdx.x;

    // stage W transposed: sW[c][o] = W[o][c]
    for (int idx = tid; idx < CH * CIN; idx += 128) {
        int o = idx >> 7, c = idx & 127;
        sW[c * QK_WS + o] = W[idx];
    }
    __syncthreads();

    float acc[CH];
#pragma unroll
    for (int o = 0; o < CH; o++) acc[o] = 0.f;

    const float* xp = x + (size_t)b * CIN * NPOS + pos;
#pragma unroll 2
    for (int c = 0; c < CIN; c++) {
        float xv = xp[(size_t)c * NPOS];
        const float* wrow = &sW[c * QK_WS];
#pragma unroll
        for (int o = 0; o < CH; o++)
            acc[o] += wrow[o] * xv;
    }

    if (mat == 2) {
#pragma unroll
        for (int o = 0; o < CH; o++)
            g_v[((size_t)b * CH + o) * NPOS + pos] = __float2half_rn(acc[o]);
    } else {
        __half* hi = (mat == 0) ? g_qh : g_kh;
        __half* lo = (mat == 0) ? g_ql : g_kl;
        size_t base = ((size_t)b * NPOS + pos) * CH;
        __half h[CH], l[CH];
#pragma unroll
        for (int o = 0; o < CH; o++) {
            h[o] = __float2half_rn(acc[o]);
            l[o] = __float2half_rn(acc[o] - __half2float(h[o]));
        }
#pragma unroll
        for (int v4 = 0; v4 < CH / 8; v4++) {
            *(uint4*)&hi[base + v4 * 8] = *(uint4*)&h[v4 * 8];
            *(uint4*)&lo[base + v4 * 8] = *(uint4*)&l[v4 * 8];
        }
    }
}

// ================= K2: scores, fp16 2-split + ldmatrix, 128-wide stats =================
// grid (32 jt, 32 it, NB), block 256 (8 warps: 2 i x 4 j).
#define SU 36                        // u32 row stride
#define SC_STAT (4 * 128 * SU)       // u32 offset of stats [4 warp_j][128 row]
#define SC_SMEM ((SC_STAT + 512) * 4)
__global__ void __launch_bounds__(256) scores_kernel()
{
    extern __shared__ u32 smu[];
    u32* sKhi = smu;
    u32* sKlo = smu + 128 * SU;
    u32* sQhi = smu + 2 * 128 * SU;
    u32* sQlo = smu + 3 * 128 * SU;
    float* sStat = (float*)(smu + SC_STAT);

    int b  = blockIdx.z;
    int i0 = blockIdx.y * 128;
    int j0 = blockIdx.x * 128;
    int tid = threadIdx.x, wid = tid >> 5, lane = tid & 31;
    int gid = lane >> 2, ctid = lane & 3;
    int warp_i = wid >> 2;                 // 0..1
    int warp_j = wid & 3;                  // 0..3
    int ibase = warp_i * 64, jbase = warp_j * 32;

    {
        const uint4* khi = (const uint4*)(g_kh + ((size_t)b * NPOS + i0) * CH);
        const uint4* klo = (const uint4*)(g_kl + ((size_t)b * NPOS + i0) * CH);
        const uint4* qhi = (const uint4*)(g_qh + ((size_t)b * NPOS + j0) * CH);
        const uint4* qlo = (const uint4*)(g_ql + ((size_t)b * NPOS + j0) * CH);
        for (int idx = tid; idx < 1024; idx += 256) {
            int row = idx >> 3, q4 = (idx & 7) * 4;
            *(uint4*)&sKhi[row * SU + q4] = khi[idx];
            *(uint4*)&sKlo[row * SU + q4] = klo[idx];
            *(uint4*)&sQhi[row * SU + q4] = qhi[idx];
            *(uint4*)&sQlo[row * SU + q4] = qlo[idx];
        }
    }
    __syncthreads();

    int arow = (lane & 7) + ((lane >> 3) & 1) * 8;      // A: x4
    int acol = (lane >> 4) * 4;                         // u32
    int brow = lane & 7;                                // B: x2 (lanes 0-15)
    int bcol = ((lane >> 3) & 1) * 4;
    u32 aKhi = smaddr(sKhi) + (u32)(((ibase + arow) * SU + acol) * 4);
    u32 aKlo = aKhi + 128 * SU * 4;
    u32 aQhi = smaddr(sQhi) + (u32)(((jbase + brow) * SU + bcol) * 4);
    u32 aQlo = aQhi + 128 * SU * 4;

    float cfr[4][4][4];
#pragma unroll
    for (int ti = 0; ti < 4; ti++)
#pragma unroll
        for (int tj = 0; tj < 4; tj++)
#pragma unroll
            for (int r = 0; r < 4; r++) cfr[ti][tj][r] = 0.f;

#pragma unroll
    for (int kk = 0; kk < 4; kk++) {
        u32 ahi[4][4], alo[4][4];
#pragma unroll
        for (int ti = 0; ti < 4; ti++) {
            u32 off = (u32)(ti * 16 * SU * 4 + kk * 32);
            LDSM_X4(ahi[ti][0], ahi[ti][1], ahi[ti][2], ahi[ti][3], aKhi + off);
            LDSM_X4(alo[ti][0], alo[ti][1], alo[ti][2], alo[ti][3], aKlo + off);
        }
        u32 bhi[4][2], blo[4][2];
#pragma unroll
        for (int tj = 0; tj < 4; tj++) {
            u32 off = (u32)(tj * 8 * SU * 4 + kk * 32);
            LDSM_X2(bhi[tj][0], bhi[tj][1], aQhi + off);
            LDSM_X2(blo[tj][0], blo[tj][1], aQlo + off);
        }
#pragma unroll
        for (int ti = 0; ti < 4; ti++)
#pragma unroll
            for (int tj = 0; tj < 4; tj++) {
                mma_f16(cfr[ti][tj], ahi[ti][0], ahi[ti][1], ahi[ti][2], ahi[ti][3],
                        bhi[tj][0], bhi[tj][1]);
                mma_f16(cfr[ti][tj], ahi[ti][0], ahi[ti][1], ahi[ti][2], ahi[ti][3],
                        blo[tj][0], blo[tj][1]);
                mma_f16(cfr[ti][tj], alo[ti][0], alo[ti][1], alo[ti][2], alo[ti][3],
                        bhi[tj][0], bhi[tj][1]);
            }
    }

    // ---- phase 1: per-warp 32-col maxes ----
#pragma unroll
    for (int ti = 0; ti < 4; ti++) {
        float m0 = -1e30f, m1 = -1e30f;
#pragma unroll
        for (int tj = 0; tj < 4; tj++) {
            m0 = fmaxf(m0, fmaxf(cfr[ti][tj][0], cfr[ti][tj][1]));
            m1 = fmaxf(m1, fmaxf(cfr[ti][tj][2], cfr[ti][tj][3]));
        }
#pragma unroll
        for (int o = 1; o < 4; o <<= 1) {
            m0 = fmaxf(m0, __shfl_xor_sync(0xffffffffu, m0, o));
            m1 = fmaxf(m1, __shfl_xor_sync(0xffffffffu, m1, o));
        }
        int rloc = ibase + ti * 16 + gid;
        if (ctid == 0) {
            sStat[warp_j * 128 + rloc]     = m0;
            sStat[warp_j * 128 + rloc + 8] = m1;
        }
    }
    __syncthreads();

    // ---- phase 2: 128-wide max ----
    float M0[4], M1[4];
#pragma unroll
    for (int ti = 0; ti < 4; ti++) {
        int rloc = ibase + ti * 16 + gid;
        M0[ti] = fmaxf(fmaxf(sStat[rloc], sStat[128 + rloc]),
                       fmaxf(sStat[256 + rloc], sStat[384 + rloc]));
        M1[ti] = fmaxf(fmaxf(sStat[rloc + 8], sStat[128 + rloc + 8]),
                       fmaxf(sStat[256 + rloc + 8], sStat[384 + rloc + 8]));
    }
    __syncthreads();

    // ---- phase 3: p = exp(S - M), write P, partial sums ----
    __half* Pb = g_P + (size_t)b * NPOS * NPOS;
#pragma unroll
    for (int ti = 0; ti < 4; ti++) {
        int rloc = ibase + ti * 16 + gid;
        int row0 = i0 + rloc;
        float s0 = 0.f, s1 = 0.f;
#pragma unroll
        for (int tj = 0; tj < 4; tj++) {
            float p00 = __expf(cfr[ti][tj][0] - M0[ti]);
            float p01 = __expf(cfr[ti][tj][1] - M0[ti]);
            float p10 = __expf(cfr[ti][tj][2] - M1[ti]);
            float p11 = __expf(cfr[ti][tj][3] - M1[ti]);
            s0 += p00 + p01;
            s1 += p10 + p11;
            int col = j0 + jbase + tj * 8 + 2 * ctid;
            *(__half2*)&Pb[(size_t)row0 * NPOS + col]       = __floats2half2_rn(p00, p01);
            *(__half2*)&Pb[(size_t)(row0 + 8) * NPOS + col] = __floats2half2_rn(p10, p11);
        }
#pragma unroll
        for (int o = 1; o < 4; o <<= 1) {
            s0 += __shfl_xor_sync(0xffffffffu, s0, o);
            s1 += __shfl_xor_sync(0xffffffffu, s1, o);
        }
        if (ctid == 0) {
            sStat[warp_j * 128 + rloc]     = s0;
            sStat[warp_j * 128 + rloc + 8] = s1;
        }
    }
    __syncthreads();

    // ---- phase 4: final stats ----
    if (warp_j == 0 && ctid == 0) {
        size_t sbase = ((size_t)b * JB + blockIdx.x) * NPOS + i0;
#pragma unroll
        for (int ti = 0; ti < 4; ti++) {
            int rloc = ibase + ti * 16 + gid;
            float s0 = sStat[rloc] + sStat[128 + rloc] + sStat[256 + rloc] + sStat[384 + rloc];
            float s1 = sStat[rloc + 8] + sStat[128 + rloc + 8] +
                       sStat[256 + rloc + 8] + sStat[384 + rloc + 8];
            g_mpart[sbase + rloc]     = M0[ti];
            g_spart[sbase + rloc]     = s0;
            g_mpart[sbase + rloc + 8] = M1[ti];
            g_spart[sbase + rloc + 8] = s1;
        }
    }
}

// ================= K3: combine stats =================
__global__ void __launch_bounds__(256) combine_kernel()
{
    int e = blockIdx.x * 256 + threadIdx.x;
    if (e >= NB * NPOS) return;
    int b = e / NPOS, i = e % NPOS;
    const float* mp = g_mpart + (size_t)b * JB * NPOS + i;
    const float* sp = g_spart + (size_t)b * JB * NPOS + i;
    float m = -1e30f;
#pragma unroll 8
    for (int jb = 0; jb < JB; jb++) m = fmaxf(m, mp[(size_t)jb * NPOS]);
    float s = 0.f;
#pragma unroll 8
    for (int jb = 0; jb < JB; jb++)
        s += __expf(mp[(size_t)jb * NPOS] - m) * sp[(size_t)jb * NPOS];
    g_m[e] = m;
    g_w[e] = 1.f / s;
}

// ================= K4: agg, fully software-pipelined =================
// grid (32 jt, ASPLIT, NB), block 256 (8 warps: 2 c x 4 j).
#define AU 36
#define PST 136                      // half stride of sP rows
#define PBUF_BYTES (64 * PST * 2)    // 17408
#define AG_PT  (64 * AU)             // u32 offset of P ring (2 buffers)
#define AG_F   (AG_PT + 2 * (PBUF_BYTES / 4))
#define AG_SMEM ((AG_F + 128) * 4)
__global__ void __launch_bounds__(256, 4) agg_kernel()
{
    extern __shared__ u32 smu[];
    u32* sV = smu;                     // [64 c][36]
    __half* sPh = (__half*)(smu + AG_PT);  // 2 x [64 i][136]
    float* sF2 = (float*)(smu + AG_F);     // [2][64]

    int b  = blockIdx.z;
    int ks = blockIdx.y;
    int jblk = blockIdx.x;
    int j0 = jblk * 128;
    const int IRANGE = NPOS / ASPLIT;       // 512
    const int NCK = IRANGE / 64;            // 8
    int ibase_g = ks * IRANGE;

    int tid = threadIdx.x, wid = tid >> 5, lane = tid & 31;
    int gid = lane >> 2, ctid = lane & 3;
    int warp_c = wid >> 2;                  // 0..1
    int warp_j = wid & 3;                   // 0..3
    int cbase = warp_c * 32, jbase = warp_j * 32;

    const __half* vb = g_v + (size_t)b * CH * NPOS;
    const __half* Pb = g_P + (size_t)b * NPOS * NPOS;
    const float* mpB = g_mpart + ((size_t)b * JB + jblk) * NPOS;
    const float* mB  = g_m + (size_t)b * NPOS;
    const float* wB  = g_w + (size_t)b * NPOS;

    int arow = (lane & 7) + ((lane >> 3) & 1) * 8;
    int acol = (lane >> 4) * 4;
    u32 aV = smaddr(sV) + (u32)(((cbase + arow) * AU + acol) * 4);
    int browP = lane & 15;
    u32 aPbase = smaddr(sPh) + (u32)((browP * PST + jbase) * 2);
    u32 pRing = smaddr(sPh);

    int stc[4], sti[4];
#pragma unroll
    for (int t = 0; t < 4; t++) {
        int idx = tid + t * 256;
        stc[t] = idx >> 4;
        sti[t] = (idx & 15) * 4;
    }

    float cfr[2][4][4];
#pragma unroll
    for (int ti = 0; ti < 2; ti++)
#pragma unroll
        for (int tj = 0; tj < 4; tj++)
#pragma unroll
            for (int r = 0; r < 4; r++) cfr[ti][tj][r] = 0.f;

    // ---- prologue ----
    for (int idx = tid; idx < 1024; idx += 256) {
        int ii = idx >> 4, j16 = idx & 15;
        cp_async16(pRing + (u32)((ii * PST + j16 * 8) * 2),
                   Pb + (size_t)(ibase_g + ii) * NPOS + j0 + j16 * 8);
    }
    CP_COMMIT();
    if (tid < 64) {
        int i = ibase_g + tid;
        sF2[tid] = __expf(mpB[i] - mB[i]) * wB[i];
    }
    uint2 vreg[4];
#pragma unroll
    for (int t = 0; t < 4; t++)
        vreg[t] = *(const uint2*)(vb + (size_t)stc[t] * NPOS + ibase_g + sti[t]);

#pragma unroll 1
    for (int ck = 0; ck < NCK; ck++) {
        int i0 = ibase_g + ck * 64;
        int cur = ck & 1;
        __syncthreads();
        {
            __half* dV = (__half*)sV;
            const float* f = sF2 + cur * 64;
#pragma unroll
            for (int t = 0; t < 4; t++) {
                __half* hh = (__half*)&vreg[t];
                __half oh[4];
#pragma unroll
                for (int u = 0; u < 4; u++)
                    oh[u] = __float2half_rn(__half2float(hh[u]) * f[sti[t] + u]);
                *(uint2*)(dV + stc[t] * (2 * AU) + sti[t]) = *(uint2*)oh;
            }
        }
        if (ck + 1 < NCK) {
            int i0n = i0 + 64;
            if (tid < 64) {
                int i = i0n + tid;
                sF2[(cur ^ 1) * 64 + tid] = __expf(mpB[i] - mB[i]) * wB[i];
            }
            u32 dbase = pRing + (u32)((cur ^ 1) * PBUF_BYTES);
            for (int idx = tid; idx < 1024; idx += 256) {
                int ii = idx >> 4, j16 = idx & 15;
                cp_async16(dbase + (u32)((ii * PST + j16 * 8) * 2),
                           Pb + (size_t)(i0n + ii) * NPOS + j0 + j16 * 8);
            }
            CP_COMMIT();
#pragma unroll
            for (int t = 0; t < 4; t++)
                vreg[t] = *(const uint2*)(vb + (size_t)stc[t] * NPOS + i0n + sti[t]);
            CP_WAIT(1);
        } else {
            CP_WAIT(0);
        }
        __syncthreads();

        u32 aP = aPbase + (u32)(cur * PBUF_BYTES);
#pragma unroll
        for (int kk = 0; kk < 4; kk++) {
            u32 av[2][4];
#pragma unroll
            for (int ti = 0; ti < 2; ti++) {
                u32 off = (u32)(ti * 16 * AU * 4 + kk * 32);
                LDSM_X4(av[ti][0], av[ti][1], av[ti][2], av[ti][3], aV + off);
            }
            u32 bb[4][2];
#pragma unroll
            for (int tj = 0; tj < 4; tj++) {
                u32 off = (u32)(kk * 16 * PST * 2 + tj * 16);
                LDSM_X2T(bb[tj][0], bb[tj][1], aP + off);
            }
#pragma unroll
            for (int ti = 0; ti < 2; ti++)
#pragma unroll
                for (int tj = 0; tj < 4; tj++)
                    mma_f16(cfr[ti][tj], av[ti][0], av[ti][1], av[ti][2], av[ti][3],
                            bb[tj][0], bb[tj][1]);
        }
    }

    float* ap = g_aggp[ks] + (size_t)b * CH * NPOS;
#pragma unroll
    for (int ti = 0; ti < 2; ti++) {
        int c0 = cbase + ti * 16 + gid;
#pragma unroll
        for (int tj = 0; tj < 4; tj++) {
            int col = j0 + jbase + tj * 8 + 2 * ctid;
            *(float2*)&ap[(size_t)c0 * NPOS + col] =
                make_float2(cfr[ti][tj][0], cfr[ti][tj][1]);
            *(float2*)&ap[(size_t)(c0 + 8) * NPOS + col] =
                make_float2(cfr[ti][tj][2], cfr[ti][tj][3]);
        }
    }
}

// ================= K5: fused reduce + post =================
#define PF_W   0                      // [128 o][64 c]
#define PF_A   (128 * 64)             // [64 c][132]
#define PF_SMEM ((PF_A + 64 * 132) * 4)
__global__ void __launch_bounds__(256) post_fused_kernel(
    const float* __restrict__ x,
    const float* __restrict__ Wpost,
    float* __restrict__ out)
{
    extern __shared__ float smf[];
    float* sW = smf + PF_W;
    float* sA = smf + PF_A;

    int b  = blockIdx.x;
    int p0 = blockIdx.y * 128;
    int tid = threadIdx.x;

    for (int idx = tid; idx < 2048; idx += 256)
        *(float4*)&sW[idx * 4] = *(const float4*)&Wpost[idx * 4];

    for (int idx = tid; idx < 2048; idx += 256) {
        int c = idx >> 5, p4 = (idx & 31) * 4;
        size_t off = ((size_t)b * CH + c) * NPOS + p0 + p4;
        float4 s = *(const float4*)&g_aggp[0][off];
#pragma unroll
        for (int ks = 1; ks < ASPLIT; ks++) {
            float4 t = *(const float4*)&g_aggp[ks][off];
            s.x += t.x; s.y += t.y; s.z += t.z; s.w += t.w;
        }
        *(float4*)&sA[c * 132 + p4] = s;
    }
    __syncthreads();

    int half = tid >> 7;
    int pos  = tid & 127;
    int obase = half * 64;

    float acc[64];
#pragma unroll
    for (int o = 0; o < 64; o++) acc[o] = 0.f;
#pragma unroll 4
    for (int c = 0; c < CH; c++) {
        float a = sA[c * 132 + pos];
#pragma unroll
        for (int o = 0; o < 64; o++)
            acc[o] += sW[(obase + o) * 64 + c] * a;
    }
#pragma unroll
    for (int o = 0; o < 64; o++) {
        size_t idx = ((size_t)b * CIN + obase + o) * NPOS + p0 + pos;
        out[idx] = acc[o] + x[idx];
    }
}

// ================= launch =================
extern "C" void kernel_launch(void* const* d_in, const int* in_sizes, int n_in,
                              void* d_out, int out_size)
{
    const float* x     = (const float*)d_in[0];
    const float* Wq    = (const float*)d_in[1];
    const float* Wk    = (const float*)d_in[2];
    const float* Wv    = (const float*)d_in[3];
    const float* Wpost = (const float*)d_in[4];
    float* out = (float*)d_out;

    cudaFuncSetAttribute(scores_kernel, cudaFuncAttributeMaxDynamicSharedMemorySize, SC_SMEM);
    cudaFuncSetAttribute(agg_kernel,    cudaFuncAttributeMaxDynamicSharedMemorySize, AG_SMEM);
    cudaFuncSetAttribute(post_fused_kernel, cudaFuncAttributeMaxDynamicSharedMemorySize, PF_SMEM);

    qkv_kernel<<<dim3(NB, NPOS / 128, 3), 128>>>(x, Wq, Wk, Wv);
    scores_kernel<<<dim3(NPOS / 128, NPOS / 128, NB), 256, SC_SMEM>>>();
    combine_kernel<<<(NB * NPOS + 255) / 256, 256>>>();
    agg_kernel<<<dim3(NPOS / 128, ASPLIT, NB), 256, AG_SMEM>>>();
    post_fused_kernel<<<dim3(NB, NPOS / 128), 256, PF_SMEM>>>(x, Wpost, out);
}

// round 16
// speedup vs baseline: 1.3248x; 1.3248x over previous
#include <cuda_runtime.h>
#include <cuda_fp16.h>
#include <cstdint>

#define NB   2
#define CIN  128
#define CH   64
#define NPOS 4096
#define JB   32           // 128-wide stat blocks
#define ASPLIT 8

typedef uint32_t u32;

// ================= helpers =================
__device__ __forceinline__ void mma_f16(float c[4], u32 a0, u32 a1, u32 a2, u32 a3,
                                        u32 b0, u32 b1) {
    asm volatile("mma.sync.aligned.m16n8k16.row.col.f32.f16.f16.f32 "
                 "{%0,%1,%2,%3}, {%4,%5,%6,%7}, {%8,%9}, {%0,%1,%2,%3};"
                 : "+f"(c[0]), "+f"(c[1]), "+f"(c[2]), "+f"(c[3])
                 : "r"(a0), "r"(a1), "r"(a2), "r"(a3), "r"(b0), "r"(b1));
}
__device__ __forceinline__ u32 smaddr(const void* p) {
    return (u32)__cvta_generic_to_shared(p);
}
#define LDSM_X4(r0, r1, r2, r3, a) \
    asm volatile("ldmatrix.sync.aligned.m8n8.x4.shared.b16 {%0,%1,%2,%3}, [%4];" \
        : "=r"(r0), "=r"(r1), "=r"(r2), "=r"(r3) : "r"(a))
#define LDSM_X2(r0, r1, a) \
    asm volatile("ldmatrix.sync.aligned.m8n8.x2.shared.b16 {%0,%1}, [%2];" \
        : "=r"(r0), "=r"(r1) : "r"(a))
#define LDSM_X2T(r0, r1, a) \
    asm volatile("ldmatrix.sync.aligned.m8n8.x2.trans.shared.b16 {%0,%1}, [%2];" \
        : "=r"(r0), "=r"(r1) : "r"(a))
__device__ __forceinline__ void cp_async16(u32 dst, const void* src) {
    asm volatile("cp.async.cg.shared.global [%0], [%1], 16;" :: "r"(dst), "l"(src));
}
#define CP_COMMIT() asm volatile("cp.async.commit_group;" ::: "memory")
#define CP_WAIT(n)  asm volatile("cp.async.wait_group %0;" :: "n"(n) : "memory")

// ================= scratch =================
__device__ __half g_kh[NB * NPOS * CH];     // [b][i][c]
__device__ __half g_kl[NB * NPOS * CH];
__device__ __half g_qh[NB * NPOS * CH];     // [b][j][c]
__device__ __half g_ql[NB * NPOS * CH];
__device__ __half g_v [NB * CH * NPOS];     // [b][c][i] single fp16
__device__ __half g_P [(size_t)NB * NPOS * NPOS];   // P_loc = exp(S - m_block128)
__device__ float g_mpart[NB * JB * NPOS];
__device__ float g_spart[NB * JB * NPOS];
__device__ float g_m[NB * NPOS];
__device__ float g_w[NB * NPOS];
__device__ float g_aggp[ASPLIT][NB * CH * NPOS];

// ================= K1: qkv (fp16; k/q hi+lo split), 32 oc/thread =================
// grid (NB, 32, 6), block 128.  z: mat = z>>1, o0 = (z&1)*32.
__global__ void __launch_bounds__(128) qkv_kernel(
    const float* __restrict__ x,
    const float* __restrict__ Wq,
    const float* __restrict__ Wk,
    const float* __restrict__ Wv)
{
    int b   = blockIdx.x;
    int pos = blockIdx.y * 128 + threadIdx.x;
    int z   = blockIdx.z;            // 0..5
    int mat = z >> 1;
    int o0  = (z & 1) * 32;
    const float* W = (mat == 0) ? Wq : (mat == 1) ? Wk : Wv;

    float acc[32];
#pragma unroll
    for (int u = 0; u < 32; u++) acc[u] = 0.f;
    const float* xp = x + (size_t)b * CIN * NPOS + pos;
#pragma unroll 2
    for (int c = 0; c < CIN; c++) {
        float xv = xp[(size_t)c * NPOS];
#pragma unroll
        for (int u = 0; u < 32; u++)
            acc[u] += W[(o0 + u) * CIN + c] * xv;
    }
    if (mat == 2) {
#pragma unroll
        for (int u = 0; u < 32; u++)
            g_v[((size_t)b * CH + o0 + u) * NPOS + pos] = __float2half_rn(acc[u]);
    } else {
        __half* hi = (mat == 0) ? g_qh : g_kh;
        __half* lo = (mat == 0) ? g_ql : g_kl;
        size_t base = ((size_t)b * NPOS + pos) * CH + o0;
#pragma unroll
        for (int g = 0; g < 4; g++) {
            __half h[8], l[8];
#pragma unroll
            for (int u = 0; u < 8; u++) {
                float a = acc[g * 8 + u];
                h[u] = __float2half_rn(a);
                l[u] = __float2half_rn(a - __half2float(h[u]));
            }
            *(uint4*)&hi[base + g * 8] = *(uint4*)h;
            *(uint4*)&lo[base + g * 8] = *(uint4*)l;
        }
    }
}

// ================= K2: scores, fp16 2-split + ldmatrix, 128-wide stats =================
// grid (32 jt, 32 it, NB), block 256 (8 warps: 2 i x 4 j).
#define SU 36                        // u32 row stride
#define SC_STAT (4 * 128 * SU)       // u32 offset of stats [4 warp_j][128 row]
#define SC_SMEM ((SC_STAT + 512) * 4)
__global__ void __launch_bounds__(256) scores_kernel()
{
    extern __shared__ u32 smu[];
    u32* sKhi = smu;
    u32* sKlo = smu + 128 * SU;
    u32* sQhi = smu + 2 * 128 * SU;
    u32* sQlo = smu + 3 * 128 * SU;
    float* sStat = (float*)(smu + SC_STAT);

    int b  = blockIdx.z;
    int i0 = blockIdx.y * 128;
    int j0 = blockIdx.x * 128;
    int tid = threadIdx.x, wid = tid >> 5, lane = tid & 31;
    int gid = lane >> 2, ctid = lane & 3;
    int warp_i = wid >> 2;                 // 0..1
    int warp_j = wid & 3;                  // 0..3
    int ibase = warp_i * 64, jbase = warp_j * 32;

    {
        const uint4* khi = (const uint4*)(g_kh + ((size_t)b * NPOS + i0) * CH);
        const uint4* klo = (const uint4*)(g_kl + ((size_t)b * NPOS + i0) * CH);
        const uint4* qhi = (const uint4*)(g_qh + ((size_t)b * NPOS + j0) * CH);
        const uint4* qlo = (const uint4*)(g_ql + ((size_t)b * NPOS + j0) * CH);
        for (int idx = tid; idx < 1024; idx += 256) {
            int row = idx >> 3, q4 = (idx & 7) * 4;
            *(uint4*)&sKhi[row * SU + q4] = khi[idx];
            *(uint4*)&sKlo[row * SU + q4] = klo[idx];
            *(uint4*)&sQhi[row * SU + q4] = qhi[idx];
            *(uint4*)&sQlo[row * SU + q4] = qlo[idx];
        }
    }
    __syncthreads();

    int arow = (lane & 7) + ((lane >> 3) & 1) * 8;      // A: x4
    int acol = (lane >> 4) * 4;                         // u32
    int brow = lane & 7;                                // B: x2 (lanes 0-15)
    int bcol = ((lane >> 3) & 1) * 4;
    u32 aKhi = smaddr(sKhi) + (u32)(((ibase + arow) * SU + acol) * 4);
    u32 aKlo = aKhi + 128 * SU * 4;
    u32 aQhi = smaddr(sQhi) + (u32)(((jbase + brow) * SU + bcol) * 4);
    u32 aQlo = aQhi + 128 * SU * 4;

    float cfr[4][4][4];
#pragma unroll
    for (int ti = 0; ti < 4; ti++)
#pragma unroll
        for (int tj = 0; tj < 4; tj++)
#pragma unroll
            for (int r = 0; r < 4; r++) cfr[ti][tj][r] = 0.f;

#pragma unroll
    for (int kk = 0; kk < 4; kk++) {
        u32 ahi[4][4], alo[4][4];
#pragma unroll
        for (int ti = 0; ti < 4; ti++) {
            u32 off = (u32)(ti * 16 * SU * 4 + kk * 32);
            LDSM_X4(ahi[ti][0], ahi[ti][1], ahi[ti][2], ahi[ti][3], aKhi + off);
            LDSM_X4(alo[ti][0], alo[ti][1], alo[ti][2], alo[ti][3], aKlo + off);
        }
        u32 bhi[4][2], blo[4][2];
#pragma unroll
        for (int tj = 0; tj < 4; tj++) {
            u32 off = (u32)(tj * 8 * SU * 4 + kk * 32);
            LDSM_X2(bhi[tj][0], bhi[tj][1], aQhi + off);
            LDSM_X2(blo[tj][0], blo[tj][1], aQlo + off);
        }
#pragma unroll
        for (int ti = 0; ti < 4; ti++)
#pragma unroll
            for (int tj = 0; tj < 4; tj++) {
                mma_f16(cfr[ti][tj], ahi[ti][0], ahi[ti][1], ahi[ti][2], ahi[ti][3],
                        bhi[tj][0], bhi[tj][1]);
                mma_f16(cfr[ti][tj], ahi[ti][0], ahi[ti][1], ahi[ti][2], ahi[ti][3],
                        blo[tj][0], blo[tj][1]);
                mma_f16(cfr[ti][tj], alo[ti][0], alo[ti][1], alo[ti][2], alo[ti][3],
                        bhi[tj][0], bhi[tj][1]);
            }
    }

    // ---- phase 1: per-warp 32-col maxes ----
#pragma unroll
    for (int ti = 0; ti < 4; ti++) {
        float m0 = -1e30f, m1 = -1e30f;
#pragma unroll
        for (int tj = 0; tj < 4; tj++) {
            m0 = fmaxf(m0, fmaxf(cfr[ti][tj][0], cfr[ti][tj][1]));
            m1 = fmaxf(m1, fmaxf(cfr[ti][tj][2], cfr[ti][tj][3]));
        }
#pragma unroll
        for (int o = 1; o < 4; o <<= 1) {
            m0 = fmaxf(m0, __shfl_xor_sync(0xffffffffu, m0, o));
            m1 = fmaxf(m1, __shfl_xor_sync(0xffffffffu, m1, o));
        }
        int rloc = ibase + ti * 16 + gid;
        if (ctid == 0) {
            sStat[warp_j * 128 + rloc]     = m0;
            sStat[warp_j * 128 + rloc + 8] = m1;
        }
    }
    __syncthreads();

    // ---- phase 2: 128-wide max ----
    float M0[4], M1[4];
#pragma unroll
    for (int ti = 0; ti < 4; ti++) {
        int rloc = ibase + ti * 16 + gid;
        M0[ti] = fmaxf(fmaxf(sStat[rloc], sStat[128 + rloc]),
                       fmaxf(sStat[256 + rloc], sStat[384 + rloc]));
        M1[ti] = fmaxf(fmaxf(sStat[rloc + 8], sStat[128 + rloc + 8]),
                       fmaxf(sStat[256 + rloc + 8], sStat[384 + rloc + 8]));
    }
    __syncthreads();

    // ---- phase 3: p = exp(S - M), write P, partial sums ----
    __half* Pb = g_P + (size_t)b * NPOS * NPOS;
#pragma unroll
    for (int ti = 0; ti < 4; ti++) {
        int rloc = ibase + ti * 16 + gid;
        int row0 = i0 + rloc;
        float s0 = 0.f, s1 = 0.f;
#pragma unroll
        for (int tj = 0; tj < 4; tj++) {
            float p00 = __expf(cfr[ti][tj][0] - M0[ti]);
            float p01 = __expf(cfr[ti][tj][1] - M0[ti]);
            float p10 = __expf(cfr[ti][tj][2] - M1[ti]);
            float p11 = __expf(cfr[ti][tj][3] - M1[ti]);
            s0 += p00 + p01;
            s1 += p10 + p11;
            int col = j0 + jbase + tj * 8 + 2 * ctid;
            *(__half2*)&Pb[(size_t)row0 * NPOS + col]       = __floats2half2_rn(p00, p01);
            *(__half2*)&Pb[(size_t)(row0 + 8) * NPOS + col] = __floats2half2_rn(p10, p11);
        }
#pragma unroll
        for (int o = 1; o < 4; o <<= 1) {
            s0 += __shfl_xor_sync(0xffffffffu, s0, o);
            s1 += __shfl_xor_sync(0xffffffffu, s1, o);
        }
        if (ctid == 0) {
            sStat[warp_j * 128 + rloc]     = s0;
            sStat[warp_j * 128 + rloc + 8] = s1;
        }
    }
    __syncthreads();

    // ---- phase 4: final stats ----
    if (warp_j == 0 && ctid == 0) {
        size_t sbase = ((size_t)b * JB + blockIdx.x) * NPOS + i0;
#pragma unroll
        for (int ti = 0; ti < 4; ti++) {
            int rloc = ibase + ti * 16 + gid;
            float s0 = sStat[rloc] + sStat[128 + rloc] + sStat[256 + rloc] + sStat[384 + rloc];
            float s1 = sStat[rloc + 8] + sStat[128 + rloc + 8] +
                       sStat[256 + rloc + 8] + sStat[384 + rloc + 8];
            g_mpart[sbase + rloc]     = M0[ti];
            g_spart[sbase + rloc]     = s0;
            g_mpart[sbase + rloc + 8] = M1[ti];
            g_spart[sbase + rloc + 8] = s1;
        }
    }
}

// ================= K3: combine stats =================
__global__ void __launch_bounds__(256) combine_kernel()
{
    int e = blockIdx.x * 256 + threadIdx.x;
    if (e >= NB * NPOS) return;
    int b = e / NPOS, i = e % NPOS;
    const float* mp = g_mpart + (size_t)b * JB * NPOS + i;
    const float* sp = g_spart + (size_t)b * JB * NPOS + i;
    float m = -1e30f;
#pragma unroll 8
    for (int jb = 0; jb < JB; jb++) m = fmaxf(m, mp[(size_t)jb * NPOS]);
    float s = 0.f;
#pragma unroll 8
    for (int jb = 0; jb < JB; jb++)
        s += __expf(mp[(size_t)jb * NPOS] - m) * sp[(size_t)jb * NPOS];
    g_m[e] = m;
    g_w[e] = 1.f / s;
}

// ================= K4: agg, fully software-pipelined =================
// grid (32 jt, ASPLIT, NB), block 256 (8 warps: 2 c x 4 j).
#define AU 36
#define PST 136                      // half stride of sP rows
#define PBUF_BYTES (64 * PST * 2)    // 17408
#define AG_PT  (64 * AU)             // u32 offset of P ring (2 buffers)
#define AG_F   (AG_PT + 2 * (PBUF_BYTES / 4))
#define AG_SMEM ((AG_F + 128) * 4)
__global__ void __launch_bounds__(256, 4) agg_kernel()
{
    extern __shared__ u32 smu[];
    u32* sV = smu;                     // [64 c][36]
    __half* sPh = (__half*)(smu + AG_PT);  // 2 x [64 i][136]
    float* sF2 = (float*)(smu + AG_F);     // [2][64]

    int b  = blockIdx.z;
    int ks = blockIdx.y;
    int jblk = blockIdx.x;
    int j0 = jblk * 128;
    const int IRANGE = NPOS / ASPLIT;       // 512
    const int NCK = IRANGE / 64;            // 8
    int ibase_g = ks * IRANGE;

    int tid = threadIdx.x, wid = tid >> 5, lane = tid & 31;
    int gid = lane >> 2, ctid = lane & 3;
    int warp_c = wid >> 2;                  // 0..1
    int warp_j = wid & 3;                   // 0..3
    int cbase = warp_c * 32, jbase = warp_j * 32;

    const __half* vb = g_v + (size_t)b * CH * NPOS;
    const __half* Pb = g_P + (size_t)b * NPOS * NPOS;
    const float* mpB = g_mpart + ((size_t)b * JB + jblk) * NPOS;
    const float* mB  = g_m + (size_t)b * NPOS;
    const float* wB  = g_w + (size_t)b * NPOS;

    int arow = (lane & 7) + ((lane >> 3) & 1) * 8;
    int acol = (lane >> 4) * 4;
    u32 aV = smaddr(sV) + (u32)(((cbase + arow) * AU + acol) * 4);
    int browP = lane & 15;
    u32 aPbase = smaddr(sPh) + (u32)((browP * PST + jbase) * 2);
    u32 pRing = smaddr(sPh);

    int stc[4], sti[4];
#pragma unroll
    for (int t = 0; t < 4; t++) {
        int idx = tid + t * 256;
        stc[t] = idx >> 4;
        sti[t] = (idx & 15) * 4;
    }

    float cfr[2][4][4];
#pragma unroll
    for (int ti = 0; ti < 2; ti++)
#pragma unroll
        for (int tj = 0; tj < 4; tj++)
#pragma unroll
            for (int r = 0; r < 4; r++) cfr[ti][tj][r] = 0.f;

    // ---- prologue ----
    for (int idx = tid; idx < 1024; idx += 256) {
        int ii = idx >> 4, j16 = idx & 15;
        cp_async16(pRing + (u32)((ii * PST + j16 * 8) * 2),
                   Pb + (size_t)(ibase_g + ii) * NPOS + j0 + j16 * 8);
    }
    CP_COMMIT();
    if (tid < 64) {
        int i = ibase_g + tid;
        sF2[tid] = __expf(mpB[i] - mB[i]) * wB[i];
    }
    uint2 vreg[4];
#pragma unroll
    for (int t = 0; t < 4; t++)
        vreg[t] = *(const uint2*)(vb + (size_t)stc[t] * NPOS + ibase_g + sti[t]);

#pragma unroll 1
    for (int ck = 0; ck < NCK; ck++) {
        int i0 = ibase_g + ck * 64;
        int cur = ck & 1;
        __syncthreads();
        {
            __half* dV = (__half*)sV;
            const float* f = sF2 + cur * 64;
#pragma unroll
            for (int t = 0; t < 4; t++) {
                __half* hh = (__half*)&vreg[t];
                __half oh[4];
#pragma unroll
                for (int u = 0; u < 4; u++)
                    oh[u] = __float2half_rn(__half2float(hh[u]) * f[sti[t] + u]);
                *(uint2*)(dV + stc[t] * (2 * AU) + sti[t]) = *(uint2*)oh;
            }
        }
        if (ck + 1 < NCK) {
            int i0n = i0 + 64;
            if (tid < 64) {
                int i = i0n + tid;
                sF2[(cur ^ 1) * 64 + tid] = __expf(mpB[i] - mB[i]) * wB[i];
            }
            u32 dbase = pRing + (u32)((cur ^ 1) * PBUF_BYTES);
            for (int idx = tid; idx < 1024; idx += 256) {
                int ii = idx >> 4, j16 = idx & 15;
                cp_async16(dbase + (u32)((ii * PST + j16 * 8) * 2),
                           Pb + (size_t)(i0n + ii) * NPOS + j0 + j16 * 8);
            }
            CP_COMMIT();
#pragma unroll
            for (int t = 0; t < 4; t++)
                vreg[t] = *(const uint2*)(vb + (size_t)stc[t] * NPOS + i0n + sti[t]);
            CP_WAIT(1);
        } else {
            CP_WAIT(0);
        }
        __syncthreads();

        u32 aP = aPbase + (u32)(cur * PBUF_BYTES);
#pragma unroll
        for (int kk = 0; kk < 4; kk++) {
            u32 av[2][4];
#pragma unroll
            for (int ti = 0; ti < 2; ti++) {
                u32 off = (u32)(ti * 16 * AU * 4 + kk * 32);
                LDSM_X4(av[ti][0], av[ti][1], av[ti][2], av[ti][3], aV + off);
            }
            u32 bb[4][2];
#pragma unroll
            for (int tj = 0; tj < 4; tj++) {
                u32 off = (u32)(kk * 16 * PST * 2 + tj * 16);
                LDSM_X2T(bb[tj][0], bb[tj][1], aP + off);
            }
#pragma unroll
            for (int ti = 0; ti < 2; ti++)
#pragma unroll
                for (int tj = 0; tj < 4; tj++)
                    mma_f16(cfr[ti][tj], av[ti][0], av[ti][1], av[ti][2], av[ti][3],
                            bb[tj][0], bb[tj][1]);
        }
    }

    float* ap = g_aggp[ks] + (size_t)b * CH * NPOS;
#pragma unroll
    for (int ti = 0; ti < 2; ti++) {
        int c0 = cbase + ti * 16 + gid;
#pragma unroll
        for (int tj = 0; tj < 4; tj++) {
            int col = j0 + jbase + tj * 8 + 2 * ctid;
            *(float2*)&ap[(size_t)c0 * NPOS + col] =
                make_float2(cfr[ti][tj][0], cfr[ti][tj][1]);
            *(float2*)&ap[(size_t)(c0 + 8) * NPOS + col] =
                make_float2(cfr[ti][tj][2], cfr[ti][tj][3]);
        }
    }
}

// ================= K5: fused reduce + post =================
#define PF_W   0                      // [128 o][64 c]
#define PF_A   (128 * 64)             // [64 c][132]
#define PF_SMEM ((PF_A + 64 * 132) * 4)
__global__ void __launch_bounds__(256) post_fused_kernel(
    const float* __restrict__ x,
    const float* __restrict__ Wpost,
    float* __restrict__ out)
{
    extern __shared__ float smf[];
    float* sW = smf + PF_W;
    float* sA = smf + PF_A;

    int b  = blockIdx.x;
    int p0 = blockIdx.y * 128;
    int tid = threadIdx.x;

    for (int idx = tid; idx < 2048; idx += 256)
        *(float4*)&sW[idx * 4] = *(const float4*)&Wpost[idx * 4];

    for (int idx = tid; idx < 2048; idx += 256) {
        int c = idx >> 5, p4 = (idx & 31) * 4;
        size_t off = ((size_t)b * CH + c) * NPOS + p0 + p4;
        float4 s = *(const float4*)&g_aggp[0][off];
#pragma unroll
        for (int ks = 1; ks < ASPLIT; ks++) {
            float4 t = *(const float4*)&g_aggp[ks][off];
            s.x += t.x; s.y += t.y; s.z += t.z; s.w += t.w;
        }
        *(float4*)&sA[c * 132 + p4] = s;
    }
    __syncthreads();

    int half = tid >> 7;
    int pos  = tid & 127;
    int obase = half * 64;

    float acc[64];
#pragma unroll
    for (int o = 0; o < 64; o++) acc[o] = 0.f;
#pragma unroll 4
    for (int c = 0; c < CH; c++) {
        float a = sA[c * 132 + pos];
#pragma unroll
        for (int o = 0; o < 64; o++)
            acc[o] += sW[(obase + o) * 64 + c] * a;
    }
#pragma unroll
    for (int o = 0; o < 64; o++) {
        size_t idx = ((size_t)b * CIN + obase + o) * NPOS + p0 + pos;
        out[idx] = acc[o] + x[idx];
    }
}

// ================= launch =================
extern "C" void kernel_launch(void* const* d_in, const int* in_sizes, int n_in,
                              void* d_out, int out_size)
{
    const float* x     = (const float*)d_in[0];
    const float* Wq    = (const float*)d_in[1];
    const float* Wk    = (const float*)d_in[2];
    const float* Wv    = (const float*)d_in[3];
    const float* Wpost = (const float*)d_in[4];
    float* out = (float*)d_out;

    cudaFuncSetAttribute(scores_kernel, cudaFuncAttributeMaxDynamicSharedMemorySize, SC_SMEM);
    cudaFuncSetAttribute(agg_kernel,    cudaFuncAttributeMaxDynamicSharedMemorySize, AG_SMEM);
    cudaFuncSetAttribute(post_fused_kernel, cudaFuncAttributeMaxDynamicSharedMemorySize, PF_SMEM);

    qkv_kernel<<<dim3(NB, NPOS / 128, 6), 128>>>(x, Wq, Wk, Wv);
    scores_kernel<<<dim3(NPOS / 128, NPOS / 128, NB), 256, SC_SMEM>>>();
    combine_kernel<<<(NB * NPOS + 255) / 256, 256>>>();
    agg_kernel<<<dim3(NPOS / 128, ASPLIT, NB), 256, AG_SMEM>>>();
    post_fused_kernel<<<dim3(NB, NPOS / 128), 256, PF_SMEM>>>(x, Wpost, out);
}

// round 17
// speedup vs baseline: 1.5083x; 1.1385x over previous
#include <cuda_runtime.h>
#include <cuda_fp16.h>
#include <cstdint>

#define NB   2
#define CIN  128
#define CH   64
#define NPOS 4096
#define JB   32           // 128-wide stat blocks
#define ASPLIT 8

typedef uint32_t u32;

// ================= helpers =================
__device__ __forceinline__ void mma_f16(float c[4], u32 a0, u32 a1, u32 a2, u32 a3,
                                        u32 b0, u32 b1) {
    asm volatile("mma.sync.aligned.m16n8k16.row.col.f32.f16.f16.f32 "
                 "{%0,%1,%2,%3}, {%4,%5,%6,%7}, {%8,%9}, {%0,%1,%2,%3};"
                 : "+f"(c[0]), "+f"(c[1]), "+f"(c[2]), "+f"(c[3])
                 : "r"(a0), "r"(a1), "r"(a2), "r"(a3), "r"(b0), "r"(b1));
}
__device__ __forceinline__ u32 smaddr(const void* p) {
    return (u32)__cvta_generic_to_shared(p);
}
#define LDSM_X4(r0, r1, r2, r3, a) \
    asm volatile("ldmatrix.sync.aligned.m8n8.x4.shared.b16 {%0,%1,%2,%3}, [%4];" \
        : "=r"(r0), "=r"(r1), "=r"(r2), "=r"(r3) : "r"(a))
#define LDSM_X2(r0, r1, a) \
    asm volatile("ldmatrix.sync.aligned.m8n8.x2.shared.b16 {%0,%1}, [%2];" \
        : "=r"(r0), "=r"(r1) : "r"(a))
#define LDSM_X2T(r0, r1, a) \
    asm volatile("ldmatrix.sync.aligned.m8n8.x2.trans.shared.b16 {%0,%1}, [%2];" \
        : "=r"(r0), "=r"(r1) : "r"(a))
__device__ __forceinline__ void cp_async16(u32 dst, const void* src) {
    asm volatile("cp.async.cg.shared.global [%0], [%1], 16;" :: "r"(dst), "l"(src));
}
#define CP_COMMIT() asm volatile("cp.async.commit_group;" ::: "memory")
#define CP_WAIT(n)  asm volatile("cp.async.wait_group %0;" :: "n"(n) : "memory")

// ================= scratch =================
__device__ __half g_kh[NB * NPOS * CH];     // [b][i][c]
__device__ __half g_kl[NB * NPOS * CH];
__device__ __half g_qh[NB * NPOS * CH];     // [b][j][c]
__device__ __half g_ql[NB * NPOS * CH];
__device__ __half g_v [NB * CH * NPOS];     // [b][c][i] single fp16
__device__ __half g_P [(size_t)NB * NPOS * NPOS];   // P_loc = exp(S - m_block128)
__device__ float g_mpart[NB * JB * NPOS];
__device__ float g_spart[NB * JB * NPOS];
__device__ float g_m[NB * NPOS];
__device__ float g_w[NB * NPOS];
__device__ float g_aggp[ASPLIT][NB * CH * NPOS];

// ================= K1: qkv (fp16; k/q hi+lo split) — R14 version =================
__global__ void __launch_bounds__(128) qkv_kernel(
    const float* __restrict__ x,
    const float* __restrict__ Wq,
    const float* __restrict__ Wk,
    const float* __restrict__ Wv)
{
    int b   = blockIdx.x;
    int pos = blockIdx.y * 128 + threadIdx.x;
    int z   = blockIdx.z;            // 0..23
    int mat = z >> 3;
    int o0  = (z & 7) * 8;
    const float* W = (mat == 0) ? Wq : (mat == 1) ? Wk : Wv;

    float acc[8];
#pragma unroll
    for (int u = 0; u < 8; u++) acc[u] = 0.f;
    const float* xp = x + (size_t)b * CIN * NPOS + pos;
#pragma unroll 4
    for (int c = 0; c < CIN; c++) {
        float xv = xp[(size_t)c * NPOS];
#pragma unroll
        for (int u = 0; u < 8; u++)
            acc[u] += W[(o0 + u) * CIN + c] * xv;
    }
    if (mat == 2) {
#pragma unroll
        for (int u = 0; u < 8; u++)
            g_v[((size_t)b * CH + o0 + u) * NPOS + pos] = __float2half_rn(acc[u]);
    } else {
        __half* hi = (mat == 0) ? g_qh : g_kh;
        __half* lo = (mat == 0) ? g_ql : g_kl;
        size_t base = ((size_t)b * NPOS + pos) * CH + o0;
        __half h[8], l[8];
#pragma unroll
        for (int u = 0; u < 8; u++) {
            h[u] = __float2half_rn(acc[u]);
            l[u] = __float2half_rn(acc[u] - __half2float(h[u]));
        }
        *(uint4*)&hi[base] = *(uint4*)h;
        *(uint4*)&lo[base] = *(uint4*)l;
    }
}

// ================= K2: scores, fp16 2-split + ldmatrix, 128-wide stats =================
// grid (32 jt, 32 it, NB), block 256 (8 warps: 2 i x 4 j).
#define SU 36                        // u32 row stride
#define SC_STAT (4 * 128 * SU)       // u32 offset of stats [4 warp_j][128 row]
#define SC_SMEM ((SC_STAT + 512) * 4)
__global__ void __launch_bounds__(256) scores_kernel()
{
    extern __shared__ u32 smu[];
    u32* sKhi = smu;
    u32* sKlo = smu + 128 * SU;
    u32* sQhi = smu + 2 * 128 * SU;
    u32* sQlo = smu + 3 * 128 * SU;
    float* sStat = (float*)(smu + SC_STAT);

    int b  = blockIdx.z;
    int i0 = blockIdx.y * 128;
    int j0 = blockIdx.x * 128;
    int tid = threadIdx.x, wid = tid >> 5, lane = tid & 31;
    int gid = lane >> 2, ctid = lane & 3;
    int warp_i = wid >> 2;                 // 0..1
    int warp_j = wid & 3;                  // 0..3
    int ibase = warp_i * 64, jbase = warp_j * 32;

    {
        const uint4* khi = (const uint4*)(g_kh + ((size_t)b * NPOS + i0) * CH);
        const uint4* klo = (const uint4*)(g_kl + ((size_t)b * NPOS + i0) * CH);
        const uint4* qhi = (const uint4*)(g_qh + ((size_t)b * NPOS + j0) * CH);
        const uint4* qlo = (const uint4*)(g_ql + ((size_t)b * NPOS + j0) * CH);
        for (int idx = tid; idx < 1024; idx += 256) {
            int row = idx >> 3, q4 = (idx & 7) * 4;
            *(uint4*)&sKhi[row * SU + q4] = khi[idx];
            *(uint4*)&sKlo[row * SU + q4] = klo[idx];
            *(uint4*)&sQhi[row * SU + q4] = qhi[idx];
            *(uint4*)&sQlo[row * SU + q4] = qlo[idx];
        }
    }
    __syncthreads();

    int arow = (lane & 7) + ((lane >> 3) & 1) * 8;      // A: x4
    int acol = (lane >> 4) * 4;                         // u32
    int brow = lane & 7;                                // B: x2 (lanes 0-15)
    int bcol = ((lane >> 3) & 1) * 4;
    u32 aKhi = smaddr(sKhi) + (u32)(((ibase + arow) * SU + acol) * 4);
    u32 aKlo = aKhi + 128 * SU * 4;
    u32 aQhi = smaddr(sQhi) + (u32)(((jbase + brow) * SU + bcol) * 4);
    u32 aQlo = aQhi + 128 * SU * 4;

    float cfr[4][4][4];
#pragma unroll
    for (int ti = 0; ti < 4; ti++)
#pragma unroll
        for (int tj = 0; tj < 4; tj++)
#pragma unroll
            for (int r = 0; r < 4; r++) cfr[ti][tj][r] = 0.f;

#pragma unroll
    for (int kk = 0; kk < 4; kk++) {
        u32 ahi[4][4], alo[4][4];
#pragma unroll
        for (int ti = 0; ti < 4; ti++) {
            u32 off = (u32)(ti * 16 * SU * 4 + kk * 32);
            LDSM_X4(ahi[ti][0], ahi[ti][1], ahi[ti][2], ahi[ti][3], aKhi + off);
            LDSM_X4(alo[ti][0], alo[ti][1], alo[ti][2], alo[ti][3], aKlo + off);
        }
        u32 bhi[4][2], blo[4][2];
#pragma unroll
        for (int tj = 0; tj < 4; tj++) {
            u32 off = (u32)(tj * 8 * SU * 4 + kk * 32);
            LDSM_X2(bhi[tj][0], bhi[tj][1], aQhi + off);
            LDSM_X2(blo[tj][0], blo[tj][1], aQlo + off);
        }
#pragma unroll
        for (int ti = 0; ti < 4; ti++)
#pragma unroll
            for (int tj = 0; tj < 4; tj++) {
                mma_f16(cfr[ti][tj], ahi[ti][0], ahi[ti][1], ahi[ti][2], ahi[ti][3],
                        bhi[tj][0], bhi[tj][1]);
                mma_f16(cfr[ti][tj], ahi[ti][0], ahi[ti][1], ahi[ti][2], ahi[ti][3],
                        blo[tj][0], blo[tj][1]);
                mma_f16(cfr[ti][tj], alo[ti][0], alo[ti][1], alo[ti][2], alo[ti][3],
                        bhi[tj][0], bhi[tj][1]);
            }
    }

    // ---- phase 1: per-warp 32-col maxes ----
#pragma unroll
    for (int ti = 0; ti < 4; ti++) {
        float m0 = -1e30f, m1 = -1e30f;
#pragma unroll
        for (int tj = 0; tj < 4; tj++) {
            m0 = fmaxf(m0, fmaxf(cfr[ti][tj][0], cfr[ti][tj][1]));
            m1 = fmaxf(m1, fmaxf(cfr[ti][tj][2], cfr[ti][tj][3]));
        }
#pragma unroll
        for (int o = 1; o < 4; o <<= 1) {
            m0 = fmaxf(m0, __shfl_xor_sync(0xffffffffu, m0, o));
            m1 = fmaxf(m1, __shfl_xor_sync(0xffffffffu, m1, o));
        }
        int rloc = ibase + ti * 16 + gid;
        if (ctid == 0) {
            sStat[warp_j * 128 + rloc]     = m0;
            sStat[warp_j * 128 + rloc + 8] = m1;
        }
    }
    __syncthreads();

    // ---- phase 2: 128-wide max ----
    float M0[4], M1[4];
#pragma unroll
    for (int ti = 0; ti < 4; ti++) {
        int rloc = ibase + ti * 16 + gid;
        M0[ti] = fmaxf(fmaxf(sStat[rloc], sStat[128 + rloc]),
                       fmaxf(sStat[256 + rloc], sStat[384 + rloc]));
        M1[ti] = fmaxf(fmaxf(sStat[rloc + 8], sStat[128 + rloc + 8]),
                       fmaxf(sStat[256 + rloc + 8], sStat[384 + rloc + 8]));
    }
    __syncthreads();

    // ---- phase 3: p = exp(S - M), write P, partial sums ----
    __half* Pb = g_P + (size_t)b * NPOS * NPOS;
#pragma unroll
    for (int ti = 0; ti < 4; ti++) {
        int rloc = ibase + ti * 16 + gid;
        int row0 = i0 + rloc;
        float s0 = 0.f, s1 = 0.f;
#pragma unroll
        for (int tj = 0; tj < 4; tj++) {
            float p00 = __expf(cfr[ti][tj][0] - M0[ti]);
            float p01 = __expf(cfr[ti][tj][1] - M0[ti]);
            float p10 = __expf(cfr[ti][tj][2] - M1[ti]);
            float p11 = __expf(cfr[ti][tj][3] - M1[ti]);
            s0 += p00 + p01;
            s1 += p10 + p11;
            int col = j0 + jbase + tj * 8 + 2 * ctid;
            *(__half2*)&Pb[(size_t)row0 * NPOS + col]       = __floats2half2_rn(p00, p01);
            *(__half2*)&Pb[(size_t)(row0 + 8) * NPOS + col] = __floats2half2_rn(p10, p11);
        }
#pragma unroll
        for (int o = 1; o < 4; o <<= 1) {
            s0 += __shfl_xor_sync(0xffffffffu, s0, o);
            s1 += __shfl_xor_sync(0xffffffffu, s1, o);
        }
        if (ctid == 0) {
            sStat[warp_j * 128 + rloc]     = s0;
            sStat[warp_j * 128 + rloc + 8] = s1;
        }
    }
    __syncthreads();

    // ---- phase 4: final stats ----
    if (warp_j == 0 && ctid == 0) {
        size_t sbase = ((size_t)b * JB + blockIdx.x) * NPOS + i0;
#pragma unroll
        for (int ti = 0; ti < 4; ti++) {
            int rloc = ibase + ti * 16 + gid;
            float s0 = sStat[rloc] + sStat[128 + rloc] + sStat[256 + rloc] + sStat[384 + rloc];
            float s1 = sStat[rloc + 8] + sStat[128 + rloc + 8] +
                       sStat[256 + rloc + 8] + sStat[384 + rloc + 8];
            g_mpart[sbase + rloc]     = M0[ti];
            g_spart[sbase + rloc]     = s0;
            g_mpart[sbase + rloc + 8] = M1[ti];
            g_spart[sbase + rloc + 8] = s1;
        }
    }
}

// ================= K3: combine stats =================
__global__ void __launch_bounds__(256) combine_kernel()
{
    int e = blockIdx.x * 256 + threadIdx.x;
    if (e >= NB * NPOS) return;
    int b = e / NPOS, i = e % NPOS;
    const float* mp = g_mpart + (size_t)b * JB * NPOS + i;
    const float* sp = g_spart + (size_t)b * JB * NPOS + i;
    float m = -1e30f;
#pragma unroll 8
    for (int jb = 0; jb < JB; jb++) m = fmaxf(m, mp[(size_t)jb * NPOS]);
    float s = 0.f;
#pragma unroll 8
    for (int jb = 0; jb < JB; jb++)
        s += __expf(mp[(size_t)jb * NPOS] - m) * sp[(size_t)jb * NPOS];
    g_m[e] = m;
    g_w[e] = 1.f / s;
}

// ================= K4: agg, fully software-pipelined =================
// grid (32 jt, ASPLIT, NB), block 256 (8 warps: 2 c x 4 j).
#define AU 36
#define PST 136                      // half stride of sP rows
#define PBUF_BYTES (64 * PST * 2)    // 17408
#define AG_PT  (64 * AU)             // u32 offset of P ring (2 buffers)
#define AG_F   (AG_PT + 2 * (PBUF_BYTES / 4))
#define AG_SMEM ((AG_F + 128) * 4)
__global__ void __launch_bounds__(256, 4) agg_kernel()
{
    extern __shared__ u32 smu[];
    u32* sV = smu;                     // [64 c][36]
    __half* sPh = (__half*)(smu + AG_PT);  // 2 x [64 i][136]
    float* sF2 = (float*)(smu + AG_F);     // [2][64]

    int b  = blockIdx.z;
    int ks = blockIdx.y;
    int jblk = blockIdx.x;
    int j0 = jblk * 128;
    const int IRANGE = NPOS / ASPLIT;       // 512
    const int NCK = IRANGE / 64;            // 8
    int ibase_g = ks * IRANGE;

    int tid = threadIdx.x, wid = tid >> 5, lane = tid & 31;
    int gid = lane >> 2, ctid = lane & 3;
    int warp_c = wid >> 2;                  // 0..1
    int warp_j = wid & 3;                   // 0..3
    int cbase = warp_c * 32, jbase = warp_j * 32;

    const __half* vb = g_v + (size_t)b * CH * NPOS;
    const __half* Pb = g_P + (size_t)b * NPOS * NPOS;
    const float* mpB = g_mpart + ((size_t)b * JB + jblk) * NPOS;
    const float* mB  = g_m + (size_t)b * NPOS;
    const float* wB  = g_w + (size_t)b * NPOS;

    int arow = (lane & 7) + ((lane >> 3) & 1) * 8;
    int acol = (lane >> 4) * 4;
    u32 aV = smaddr(sV) + (u32)(((cbase + arow) * AU + acol) * 4);
    int browP = lane & 15;
    u32 aPbase = smaddr(sPh) + (u32)((browP * PST + jbase) * 2);
    u32 pRing = smaddr(sPh);

    int stc[4], sti[4];
#pragma unroll
    for (int t = 0; t < 4; t++) {
        int idx = tid + t * 256;
        stc[t] = idx >> 4;
        sti[t] = (idx & 15) * 4;
    }

    float cfr[2][4][4];
#pragma unroll
    for (int ti = 0; ti < 2; ti++)
#pragma unroll
        for (int tj = 0; tj < 4; tj++)
#pragma unroll
            for (int r = 0; r < 4; r++) cfr[ti][tj][r] = 0.f;

    // ---- prologue ----
    for (int idx = tid; idx < 1024; idx += 256) {
        int ii = idx >> 4, j16 = idx & 15;
        cp_async16(pRing + (u32)((ii * PST + j16 * 8) * 2),
                   Pb + (size_t)(ibase_g + ii) * NPOS + j0 + j16 * 8);
    }
    CP_COMMIT();
    if (tid < 64) {
        int i = ibase_g + tid;
        sF2[tid] = __expf(mpB[i] - mB[i]) * wB[i];
    }
    uint2 vreg[4];
#pragma unroll
    for (int t = 0; t < 4; t++)
        vreg[t] = *(const uint2*)(vb + (size_t)stc[t] * NPOS + ibase_g + sti[t]);

#pragma unroll 1
    for (int ck = 0; ck < NCK; ck++) {
        int i0 = ibase_g + ck * 64;
        int cur = ck & 1;
        __syncthreads();
        {
            __half* dV = (__half*)sV;
            const float* f = sF2 + cur * 64;
#pragma unroll
            for (int t = 0; t < 4; t++) {
                __half* hh = (__half*)&vreg[t];
                __half oh[4];
#pragma unroll
                for (int u = 0; u < 4; u++)
                    oh[u] = __float2half_rn(__half2float(hh[u]) * f[sti[t] + u]);
                *(uint2*)(dV + stc[t] * (2 * AU) + sti[t]) = *(uint2*)oh;
            }
        }
        if (ck + 1 < NCK) {
            int i0n = i0 + 64;
            if (tid < 64) {
                int i = i0n + tid;
                sF2[(cur ^ 1) * 64 + tid] = __expf(mpB[i] - mB[i]) * wB[i];
            }
            u32 dbase = pRing + (u32)((cur ^ 1) * PBUF_BYTES);
            for (int idx = tid; idx < 1024; idx += 256) {
                int ii = idx >> 4, j16 = idx & 15;
                cp_async16(dbase + (u32)((ii * PST + j16 * 8) * 2),
                           Pb + (size_t)(i0n + ii) * NPOS + j0 + j16 * 8);
            }
            CP_COMMIT();
#pragma unroll
            for (int t = 0; t < 4; t++)
                vreg[t] = *(const uint2*)(vb + (size_t)stc[t] * NPOS + i0n + sti[t]);
            CP_WAIT(1);
        } else {
            CP_WAIT(0);
        }
        __syncthreads();

        u32 aP = aPbase + (u32)(cur * PBUF_BYTES);
#pragma unroll
        for (int kk = 0; kk < 4; kk++) {
            u32 av[2][4];
#pragma unroll
            for (int ti = 0; ti < 2; ti++) {
                u32 off = (u32)(ti * 16 * AU * 4 + kk * 32);
                LDSM_X4(av[ti][0], av[ti][1], av[ti][2], av[ti][3], aV + off);
            }
            u32 bb[4][2];
#pragma unroll
            for (int tj = 0; tj < 4; tj++) {
                u32 off = (u32)(kk * 16 * PST * 2 + tj * 16);
                LDSM_X2T(bb[tj][0], bb[tj][1], aP + off);
            }
#pragma unroll
            for (int ti = 0; ti < 2; ti++)
#pragma unroll
                for (int tj = 0; tj < 4; tj++)
                    mma_f16(cfr[ti][tj], av[ti][0], av[ti][1], av[ti][2], av[ti][3],
                            bb[tj][0], bb[tj][1]);
        }
    }

    float* ap = g_aggp[ks] + (size_t)b * CH * NPOS;
#pragma unroll
    for (int ti = 0; ti < 2; ti++) {
        int c0 = cbase + ti * 16 + gid;
#pragma unroll
        for (int tj = 0; tj < 4; tj++) {
            int col = j0 + jbase + tj * 8 + 2 * ctid;
            *(float2*)&ap[(size_t)c0 * NPOS + col] =
                make_float2(cfr[ti][tj][0], cfr[ti][tj][1]);
            *(float2*)&ap[(size_t)(c0 + 8) * NPOS + col] =
                make_float2(cfr[ti][tj][2], cfr[ti][tj][3]);
        }
    }
}

// ================= K5: fused reduce + post, 512 threads / 32 oc each =================
// grid (NB, 32), block 512.
#define PF_W   0                      // [128 o][64 c]
#define PF_A   (128 * 64)             // [64 c][132]
#define PF_SMEM ((PF_A + 64 * 132) * 4)
__global__ void __launch_bounds__(512) post_fused_kernel(
    const float* __restrict__ x,
    const float* __restrict__ Wpost,
    float* __restrict__ out)
{
    extern __shared__ float smf[];
    float* sW = smf + PF_W;
    float* sA = smf + PF_A;

    int b  = blockIdx.x;
    int p0 = blockIdx.y * 128;
    int tid = threadIdx.x;

    for (int idx = tid; idx < 2048; idx += 512)
        *(float4*)&sW[idx * 4] = *(const float4*)&Wpost[idx * 4];

    for (int idx = tid; idx < 2048; idx += 512) {
        int c = idx >> 5, p4 = (idx & 31) * 4;
        size_t off = ((size_t)b * CH + c) * NPOS + p0 + p4;
        float4 s = *(const float4*)&g_aggp[0][off];
#pragma unroll
        for (int ks = 1; ks < ASPLIT; ks++) {
            float4 t = *(const float4*)&g_aggp[ks][off];
            s.x += t.x; s.y += t.y; s.z += t.z; s.w += t.w;
        }
        *(float4*)&sA[c * 132 + p4] = s;
    }
    __syncthreads();

    int quarter = tid >> 7;           // 0..3
    int pos     = tid & 127;
    int obase   = quarter * 32;

    float acc[32];
#pragma unroll
    for (int o = 0; o < 32; o++) acc[o] = 0.f;
#pragma unroll 4
    for (int c = 0; c < CH; c++) {
        float a = sA[c * 132 + pos];
#pragma unroll
        for (int o = 0; o < 32; o++)
            acc[o] += sW[(obase + o) * 64 + c] * a;
    }
#pragma unroll
    for (int o = 0; o < 32; o++) {
        size_t idx = ((size_t)b * CIN + obase + o) * NPOS + p0 + pos;
        out[idx] = acc[o] + x[idx];
    }
}

// ================= launch =================
extern "C" void kernel_launch(void* const* d_in, const int* in_sizes, int n_in,
                              void* d_out, int out_size)
{
    const float* x     = (const float*)d_in[0];
    const float* Wq    = (const float*)d_in[1];
    const float* Wk    = (const float*)d_in[2];
    const float* Wv    = (const float*)d_in[3];
    const float* Wpost = (const float*)d_in[4];
    float* out = (float*)d_out;

    cudaFuncSetAttribute(scores_kernel, cudaFuncAttributeMaxDynamicSharedMemorySize, SC_SMEM);
    cudaFuncSetAttribute(agg_kernel,    cudaFuncAttributeMaxDynamicSharedMemorySize, AG_SMEM);
    cudaFuncSetAttribute(post_fused_kernel, cudaFuncAttributeMaxDynamicSharedMemorySize, PF_SMEM);

    qkv_kernel<<<dim3(NB, NPOS / 128, 24), 128>>>(x, Wq, Wk, Wv);
    scores_kernel<<<dim3(NPOS / 128, NPOS / 128, NB), 256, SC_SMEM>>>();
    combine_kernel<<<(NB * NPOS + 255) / 256, 256>>>();
    agg_kernel<<<dim3(NPOS / 128, ASPLIT, NB), 256, AG_SMEM>>>();
    post_fused_kernel<<<dim3(NB, NPOS / 128), 512, PF_SMEM>>>(x, Wpost, out);
}